// round 1
// baseline (speedup 1.0000x reference)
#include <cuda_runtime.h>
#include <math.h>

#define Hd 1024
#define Dm 512
#define Vn 50257
#define Sn 128
#define An 1024
#define Tn 25
#define SOS 1
#define NB3 ((Vn + 7) / 8)   /* 6283 blocks for logits kernel */

// ---------------- persistent device scratch (no allocs allowed) ----------------
__device__ float g_h[Hd];
__device__ float g_hnew[Hd];
__device__ float g_q[An];
__device__ float g_attn[An];
__device__ int   g_word;
__device__ float g_logZ;
__device__ unsigned long long g_blockred[NB3];

__device__ __forceinline__ float warp_sum(float v) {
#pragma unroll
    for (int o = 16; o > 0; o >>= 1) v += __shfl_down_sync(0xffffffffu, v, o);
    return v;
}

__device__ __forceinline__ unsigned long long umaxll(unsigned long long a, unsigned long long b) {
    return a > b ? a : b;
}

// ---------------- K1: GRU cell (warp per output) + fused prev-step logZ subtract ----
__global__ void k_gru(const float* __restrict__ E, const float* __restrict__ Wih,
                      const float* __restrict__ Whh, const float* __restrict__ bih,
                      const float* __restrict__ bhh, const float* __restrict__ h0,
                      float* __restrict__ out, int step)
{
    // finish previous step's log_softmax (logZ known after k_reduce of step-1)
    if (step > 0) {
        float lz = g_logZ;
        int nt = gridDim.x * blockDim.x;
        for (int v = blockIdx.x * blockDim.x + threadIdx.x; v < Vn; v += nt)
            out[(size_t)(step - 1) * Vn + v] -= lz;
    }

    int gw = (blockIdx.x * blockDim.x + threadIdx.x) >> 5;   // output index 0..1023
    int lane = threadIdx.x & 31;
    if (gw >= Hd) return;

    int word = (step == 0) ? SOS : g_word;
    const float* h = (step == 0) ? h0 : g_h;

    const float4* x4 = (const float4*)(E + (size_t)word * Dm);
    const float4* h4 = (const float4*)h;
    const float4* wr_i = (const float4*)(Wih + (size_t)gw * Dm);
    const float4* wz_i = (const float4*)(Wih + (size_t)(Hd + gw) * Dm);
    const float4* wn_i = (const float4*)(Wih + (size_t)(2 * Hd + gw) * Dm);
    const float4* wr_h = (const float4*)(Whh + (size_t)gw * Hd);
    const float4* wz_h = (const float4*)(Whh + (size_t)(Hd + gw) * Hd);
    const float4* wn_h = (const float4*)(Whh + (size_t)(2 * Hd + gw) * Hd);

    float sir = 0.f, siz = 0.f, sin_ = 0.f, shr = 0.f, shz = 0.f, shn = 0.f;
#pragma unroll
    for (int j = 0; j < Dm / 128; j++) {         // 4 iters
        float4 xv = x4[lane + 32 * j];
        float4 a = wr_i[lane + 32 * j]; sir  += a.x * xv.x + a.y * xv.y + a.z * xv.z + a.w * xv.w;
        float4 b = wz_i[lane + 32 * j]; siz  += b.x * xv.x + b.y * xv.y + b.z * xv.z + b.w * xv.w;
        float4 c = wn_i[lane + 32 * j]; sin_ += c.x * xv.x + c.y * xv.y + c.z * xv.z + c.w * xv.w;
    }
#pragma unroll
    for (int j = 0; j < Hd / 128; j++) {         // 8 iters
        float4 hv = h4[lane + 32 * j];
        float4 a = wr_h[lane + 32 * j]; shr += a.x * hv.x + a.y * hv.y + a.z * hv.z + a.w * hv.w;
        float4 b = wz_h[lane + 32 * j]; shz += b.x * hv.x + b.y * hv.y + b.z * hv.z + b.w * hv.w;
        float4 c = wn_h[lane + 32 * j]; shn += c.x * hv.x + c.y * hv.y + c.z * hv.z + c.w * hv.w;
    }
    sir = warp_sum(sir); siz = warp_sum(siz); sin_ = warp_sum(sin_);
    shr = warp_sum(shr); shz = warp_sum(shz); shn = warp_sum(shn);

    if (lane == 0) {
        float r = 1.f / (1.f + __expf(-(sir + bih[gw]          + shr + bhh[gw])));
        float z = 1.f / (1.f + __expf(-(siz + bih[Hd + gw]     + shz + bhh[Hd + gw])));
        float n = tanhf(sin_ + bih[2 * Hd + gw] + r * (shn + bhh[2 * Hd + gw]));
        g_hnew[gw] = (1.f - z) * n + z * h[gw];
    }
}

// ---------------- K2: q = Wq @ h_new (warp per output) ----------------
__global__ void k_q(const float* __restrict__ Wq)
{
    int gw = (blockIdx.x * blockDim.x + threadIdx.x) >> 5;
    int lane = threadIdx.x & 31;
    if (gw >= An) return;
    const float4* w4 = (const float4*)(Wq + (size_t)gw * Hd);
    const float4* h4 = (const float4*)g_hnew;
    float s = 0.f;
#pragma unroll
    for (int j = 0; j < 8; j++) {
        float4 a = w4[lane + 32 * j], b = h4[lane + 32 * j];
        s += a.x * b.x + a.y * b.y + a.z * b.z + a.w * b.w;
    }
    s = warp_sum(s);
    if (lane == 0) g_q[gw] = s;
}

// ---------------- K3: scores + softmax + attn (single block, all L2-hot) --------
__global__ void k_attn(const float* __restrict__ emb, float* __restrict__ out, int step)
{
    __shared__ float sc[Sn], se[Sn], sw[Sn];
    __shared__ float smax, ssum;
    int tid = threadIdx.x, lane = tid & 31, warp = tid >> 5;

    const float4* q4 = (const float4*)g_q;
    for (int si = warp; si < Sn; si += 32) {
        const float4* e4 = (const float4*)(emb + (size_t)si * An);
        float s = 0.f;
#pragma unroll
        for (int j = 0; j < 8; j++) {
            float4 a = e4[lane + 32 * j], b = q4[lane + 32 * j];
            s += a.x * b.x + a.y * b.y + a.z * b.z + a.w * b.w;
        }
        s = warp_sum(s);
        if (lane == 0) sc[si] = s;
    }
    __syncthreads();
    if (tid == 0) {
        float m = sc[0];
        for (int i = 1; i < Sn; i++) m = fmaxf(m, sc[i]);
        smax = m;
    }
    __syncthreads();
    if (tid < Sn) se[tid] = __expf(sc[tid] - smax);
    __syncthreads();
    if (tid == 0) {
        float s = 0.f;
        for (int i = 0; i < Sn; i++) s += se[i];
        ssum = s;
    }
    __syncthreads();
    if (tid < Sn) {
        float w = se[tid] / ssum;
        sw[tid] = w;
        // weights output row
        out[(size_t)Tn * Vn + (size_t)step * Sn + tid] = w;
    }
    __syncthreads();
    // attn[a] = sum_s w[s]*emb[s][a]
    float acc = 0.f;
#pragma unroll 4
    for (int si = 0; si < Sn; si++) acc += sw[si] * emb[(size_t)si * An + tid];
    g_attn[tid] = acc;
}

// ---------------- K4: logits GEMV (warp per row) + per-block argmax partials ----
__global__ void k_logits(const float* __restrict__ Wout, const float* __restrict__ bout,
                         float* __restrict__ out, int step)
{
    __shared__ __align__(16) float merge[2 * Hd];
    __shared__ unsigned long long red[8];
    int tid = threadIdx.x;
    for (int i = tid; i < Hd; i += 256) { merge[i] = g_hnew[i]; merge[Hd + i] = g_attn[i]; }
    __syncthreads();

    int warp = tid >> 5, lane = tid & 31;
    int v = blockIdx.x * 8 + warp;
    unsigned long long packed = 0ull;
    if (v < Vn) {
        const float4* w4 = (const float4*)(Wout + (size_t)v * (2 * Hd));
        const float4* m4 = (const float4*)merge;
        float s = 0.f;
#pragma unroll
        for (int j = 0; j < 16; j++) {
            float4 a = w4[lane + 32 * j], b = m4[lane + 32 * j];
            s += a.x * b.x + a.y * b.y + a.z * b.z + a.w * b.w;
        }
        s = warp_sum(s);
        if (lane == 0) {
            float logit = s + bout[v];
            out[(size_t)step * Vn + v] = logit;  // raw logit; logZ subtracted later
            unsigned int bits = __float_as_uint(logit);
            unsigned int key = (bits & 0x80000000u) ? ~bits : (bits | 0x80000000u);
            packed = ((unsigned long long)key << 32) |
                     (unsigned long long)(0xFFFFFFFFu - (unsigned)v);  // min idx on tie
        }
    }
    if (lane == 0) red[warp] = packed;
    __syncthreads();
    if (tid == 0) {
        unsigned long long m = red[0];
#pragma unroll
        for (int i = 1; i < 8; i++) m = umaxll(m, red[i]);
        g_blockred[blockIdx.x] = m;
    }
}

// ---------------- K5: argmax + logsumexp + state update (single block) ----------
__global__ void k_reduce(float* __restrict__ out, int step)
{
    __shared__ unsigned long long spk[32];
    __shared__ float spsum[32];
    __shared__ float smaxv;
    __shared__ unsigned long long sbest;
    int tid = threadIdx.x, lane = tid & 31, warp = tid >> 5;

    unsigned long long m = 0ull;
    for (int i = tid; i < NB3; i += 1024) m = umaxll(m, g_blockred[i]);
#pragma unroll
    for (int o = 16; o > 0; o >>= 1)
        m = umaxll(m, __shfl_down_sync(0xffffffffu, m, o));
    if (lane == 0) spk[warp] = m;
    __syncthreads();
    if (tid == 0) {
        unsigned long long b = spk[0];
        for (int i = 1; i < 32; i++) b = umaxll(b, spk[i]);
        sbest = b;
        unsigned int key = (unsigned int)(b >> 32);
        unsigned int bits = (key & 0x80000000u) ? (key ^ 0x80000000u) : ~key;
        smaxv = __uint_as_float(bits);
    }
    __syncthreads();

    float mx = smaxv;
    const float* lp = out + (size_t)step * Vn;
    float s = 0.f;
    for (int i = tid; i < Vn; i += 1024) s += __expf(lp[i] - mx);
    s = warp_sum(s);
    if (lane == 0) spsum[warp] = s;
    __syncthreads();
    if (tid == 0) {
        float tot = 0.f;
        for (int i = 0; i < 32; i++) tot += spsum[i];
        g_logZ = mx + logf(tot);
        int idx = (int)(0xFFFFFFFFu - (unsigned int)(sbest & 0xFFFFFFFFull));
        g_word = idx;
        out[(size_t)Tn * Vn + (size_t)Tn * Sn + step] = (float)idx;  // token
    }
    if (tid < Hd) g_h[tid] = g_hnew[tid];
}

// ---------------- K6: final-step logZ subtract ----------------
__global__ void k_sub(float* __restrict__ out, int step)
{
    int v = blockIdx.x * blockDim.x + threadIdx.x;
    if (v < Vn) out[(size_t)step * Vn + v] -= g_logZ;
}

// ---------------- launcher ----------------
extern "C" void kernel_launch(void* const* d_in, const int* in_sizes, int n_in,
                              void* d_out, int out_size)
{
    const float* hidden = (const float*)d_in[0];
    const float* emb    = (const float*)d_in[1];
    const float* E      = (const float*)d_in[2];
    const float* Wih    = (const float*)d_in[3];
    const float* Whh    = (const float*)d_in[4];
    const float* bih    = (const float*)d_in[5];
    const float* bhh    = (const float*)d_in[6];
    const float* Wq     = (const float*)d_in[7];
    const float* Wout   = (const float*)d_in[8];
    const float* bout   = (const float*)d_in[9];
    float* out = (float*)d_out;

    for (int t = 0; t < Tn; t++) {
        k_gru   <<<128, 256>>>(E, Wih, Whh, bih, bhh, hidden, out, t);
        k_q     <<<128, 256>>>(Wq);
        k_attn  <<<1, 1024>>>(emb, out, t);
        k_logits<<<NB3, 256>>>(Wout, bout, out, t);
        k_reduce<<<1, 1024>>>(out, t);
    }
    k_sub<<<(Vn + 255) / 256, 256>>>(out, Tn - 1);
}